// round 15
// baseline (speedup 1.0000x reference)
#include <cuda_runtime.h>
#include <cuda_bf16.h>
#include <cstdint>

#define D 64
#define CH 64              // rows per pipeline chunk
#define TILE 1024          // rows per CTA
#define NSTEP (TILE / CH)  // 16
#define XS 34              // u64 stride per row (32 data + 2 pad, 16B-aligned)
#define BUF (CH * XS)
#define NREP 64
#define MAX_N 100000

// ---------------- scratch (device globals) ----------------
__device__ float g_neigh[MAX_N * D];
__device__ float g_sum[2][NREP][D];
__device__ float g_sq[2][NREP][D];
__device__ __align__(16) float g_mean[2][D];
__device__ __align__(16) float g_rstd[2][D];
// k-paired weights: g_Wp[layer][kw][c] = (W[2kw][c], W[2kw+1][c]); row 16B-aligned
__device__ __align__(16) unsigned long long g_Wp[2][32][64];

// ---------------- packed fp32x2 helpers ----------------
__device__ __forceinline__ unsigned long long pack64(float lo, float hi) {
    unsigned long long r;
    asm("mov.b64 %0, {%1, %2};" : "=l"(r) : "f"(lo), "f"(hi));
    return r;
}
__device__ __forceinline__ void unpack2(unsigned long long v, float& lo, float& hi) {
    asm("mov.b64 {%0, %1}, %2;" : "=f"(lo), "=f"(hi) : "l"(v));
}
__device__ __forceinline__ unsigned long long fma2(unsigned long long a,
                                                   unsigned long long b,
                                                   unsigned long long c) {
    unsigned long long d;
    asm("fma.rn.f32x2 %0, %1, %2, %3;" : "=l"(d) : "l"(a), "l"(b), "l"(c));
    return d;
}
__device__ __forceinline__ uint32_t s2u(const void* p) {
    uint32_t a;
    asm("{ .reg .u64 t; cvta.to.shared.u64 t, %1; cvt.u32.u64 %0, t; }" : "=r"(a) : "l"(p));
    return a;
}

// ---------------- K0a: zero neigh ----------------
__global__ void zero_neigh_kernel() {
    int tid = blockIdx.x * blockDim.x + threadIdx.x;
    int stride = gridDim.x * blockDim.x;
    float4* p = (float4*)g_neigh;
    const int n4 = MAX_N * D / 4;
    for (int i = tid; i < n4; i += stride) p[i] = make_float4(0.f, 0.f, 0.f, 0.f);
}

// ---------------- K0b: zero stats + build k-paired W ----------------
__global__ void init_kernel(const float* __restrict__ W1, const float* __restrict__ W2) {
    int i = blockIdx.x * blockDim.x + threadIdx.x;
    if (i < 2 * NREP * D) {
        (&g_sum[0][0][0])[i] = 0.f;
        (&g_sq[0][0][0])[i] = 0.f;
    }
    if (i >= 2 * 32 * 64) return;
    int layer = i >> 11;
    int kw = (i >> 6) & 31;
    int c = i & 63;
    const float* W = layer ? W2 : W1;
    g_Wp[layer][kw][c] = pack64(__ldg(&W[(2 * kw) * D + c]),
                                __ldg(&W[(2 * kw + 1) * D + c]));
}

// ---------------- K1: scatter-sum  neigh[dst] += h[src] ----------------
__global__ void scatter_kernel(const float* __restrict__ h,
                               const int* __restrict__ src,
                               const int* __restrict__ dst, int E) {
    int idx = blockIdx.x * blockDim.x + threadIdx.x;
    int total = E * 16;
    if (idx >= total) return;
    int e = idx >> 4;
    int c = idx & 15;
    int s = __ldg(&src[e]);
    int d = __ldg(&dst[e]);
    float4 v = __ldg((const float4*)(h + (size_t)s * D) + c);
    float* p = g_neigh + (size_t)d * D + c * 4;
    asm volatile("red.global.add.v4.f32 [%0], {%1, %2, %3, %4};"
                 :: "l"(p), "f"(v.x), "f"(v.y), "f"(v.z), "f"(v.w) : "memory");
}

// async fill of one chunk (cp.async, zero-fill OOB tail); 256 threads
__device__ __forceinline__ void fill_async(unsigned long long* xb,
                                           const float* __restrict__ xsrc,
                                           int base, int M, int tid) {
#pragma unroll
    for (int t = 0; t < 4; ++t) {
        int idx = tid + t * 256;
        int r = idx >> 4;
        int c4 = idx & 15;
        int gr = base + r;
        unsigned long long* sp = &xb[r * XS + 2 * c4];
        if (gr < M) {
            uint32_t sa = s2u(sp);
            const float4* ga = (const float4*)(xsrc + (size_t)gr * D) + c4;
            asm volatile("cp.async.ca.shared.global [%0], [%1], 16;"
                         :: "r"(sa), "l"(ga) : "memory");
        } else {
            *(ulonglong2*)sp = make_ulonglong2(0ull, 0ull);
        }
    }
}

// sync combined fill for node tiles: v = (1+eps)h + neigh
__device__ __forceinline__ void fill_node(unsigned long long* xb,
                                          const float* __restrict__ hin,
                                          int base, int M, float epsv, int tid) {
#pragma unroll
    for (int t = 0; t < 4; ++t) {
        int idx = tid + t * 256;
        int r = idx >> 4;
        int c4 = idx & 15;
        int gr = base + r;
        float4 v = make_float4(0.f, 0.f, 0.f, 0.f);
        if (gr < M) {
            float4 a = __ldg((const float4*)(hin + (size_t)gr * D) + c4);
            float4 n = *((const float4*)(g_neigh + (size_t)gr * D) + c4);
            v.x = fmaf(epsv, a.x, n.x); v.y = fmaf(epsv, a.y, n.y);
            v.z = fmaf(epsv, a.z, n.z); v.w = fmaf(epsv, a.w, n.w);
        }
        ulonglong2 pk;
        pk.x = pack64(v.x, v.y);
        pk.y = pack64(v.z, v.w);
        *(ulonglong2*)&xb[r * XS + 2 * c4] = pk;
    }
}

#define SMEM_BYTES ((3 + 2) * BUF * 8)

// ---------------- K2: weight-stationary MLP, 2 cols/thread, single barrier/step ----------------
__global__ void __launch_bounds__(256, 1)
mlp_ws_kernel(const float* __restrict__ hin, const float* __restrict__ ein,
              const float* __restrict__ epsp,
              const float* __restrict__ b1, const float* __restrict__ b2,
              float* __restrict__ out, int N, int E, int nblk) {
    extern __shared__ unsigned long long smem[];
    unsigned long long* xs = smem;            // 3 buffers
    unsigned long long* ts = smem + 3 * BUF;  // 2 buffers

    int tid = threadIdx.x;
    int wid = tid >> 5;
    int lane = tid & 31;
    int isL2 = wid >> 2;       // warps 0-3: layer1, warps 4-7: layer2
    int wsub = wid & 3;        // row group within layer
    int c0 = 2 * lane;         // this thread's column pair
    int rbase = wsub * 16;     // 16 rows per warp per chunk

    int target, row0, M;
    float* yout;
    if (blockIdx.x < nblk) {
        target = 0; row0 = blockIdx.x * TILE; M = N; yout = out;
    } else {
        target = 1; row0 = (blockIdx.x - nblk) * TILE; M = E;
        yout = out + (size_t)N * D;
    }

    // resident weights: columns c0, c0+1, loaded as LDG.128 pairs
    unsigned long long w0[32], w1[32];
    {
        const unsigned long long* Wp = &g_Wp[isL2][0][0];
#pragma unroll
        for (int kw = 0; kw < 32; ++kw) {
            ulonglong2 wp = __ldg((const ulonglong2*)(Wp + kw * 64 + c0));
            w0[kw] = wp.x;
            w1[kw] = wp.y;
        }
    }
    const float* bias = isL2 ? b2 : b1;
    float ba = __ldg(&bias[c0]);
    float bb = __ldg(&bias[c0 + 1]);
    float epsv = target ? 1.f : (1.f + __ldg(&epsp[0]));

    float cs0 = 0.f, cs1 = 0.f, cq0 = 0.f, cq1 = 0.f;

    if (target) fill_async(xs, ein, row0, M, tid);
    else        fill_node(xs, hin, row0, M, epsv, tid);
    asm volatile("cp.async.commit_group;" ::: "memory");

    int bfill = 1, bcomp = 0;
    for (int s = 0; s <= NSTEP; ++s) {
        if (s + 1 < NSTEP) {
            if (target) fill_async(xs + bfill * BUF, ein, row0 + (s + 1) * CH, M, tid);
            else        fill_node(xs + bfill * BUF, hin, row0 + (s + 1) * CH, M, epsv, tid);
        }
        asm volatile("cp.async.commit_group;" ::: "memory");
        asm volatile("cp.async.wait_group 1;" ::: "memory");
        __syncthreads();   // xs[bcomp] visible to all; ts[s-1] writes visible to L2

        if (!isL2) {
            if (s < NSTEP) {
                const unsigned long long* xb = xs + bcomp * BUF;
                float* tb = (float*)(ts + (s & 1) * BUF);
#pragma unroll
                for (int rr = 0; rr < 16; rr += 2) {
                    int r0 = rbase + rr;
                    int r1 = r0 + 1;
                    unsigned long long a00 = 0ull, a01 = 0ull, a10 = 0ull, a11 = 0ull;
#pragma unroll
                    for (int kc = 0; kc < 16; ++kc) {
                        ulonglong2 x0 = *(const ulonglong2*)&xb[r0 * XS + 2 * kc];
                        ulonglong2 x1 = *(const ulonglong2*)&xb[r1 * XS + 2 * kc];
                        a00 = fma2(x0.x, w0[2 * kc], a00);
                        a01 = fma2(x0.x, w1[2 * kc], a01);
                        a10 = fma2(x1.x, w0[2 * kc], a10);
                        a11 = fma2(x1.x, w1[2 * kc], a11);
                        a00 = fma2(x0.y, w0[2 * kc + 1], a00);
                        a01 = fma2(x0.y, w1[2 * kc + 1], a01);
                        a10 = fma2(x1.y, w0[2 * kc + 1], a10);
                        a11 = fma2(x1.y, w1[2 * kc + 1], a11);
                    }
                    float lo, hi, t0, t1;
                    unpack2(a00, lo, hi); t0 = fmaxf(lo + hi + ba, 0.f);
                    unpack2(a01, lo, hi); t1 = fmaxf(lo + hi + bb, 0.f);
                    *(float2*)&tb[r0 * (2 * XS) + c0] = make_float2(t0, t1);
                    unpack2(a10, lo, hi); t0 = fmaxf(lo + hi + ba, 0.f);
                    unpack2(a11, lo, hi); t1 = fmaxf(lo + hi + bb, 0.f);
                    *(float2*)&tb[r1 * (2 * XS) + c0] = make_float2(t0, t1);
                }
            }
        } else {
            if (s >= 1) {
                int sc = s - 1;
                int base = row0 + sc * CH;
                const unsigned long long* tb = ts + (sc & 1) * BUF;
#pragma unroll
                for (int rr = 0; rr < 16; rr += 2) {
                    int r0 = rbase + rr;
                    int r1 = r0 + 1;
                    unsigned long long a00 = 0ull, a01 = 0ull, a10 = 0ull, a11 = 0ull;
#pragma unroll
                    for (int kc = 0; kc < 16; ++kc) {
                        ulonglong2 x0 = *(const ulonglong2*)&tb[r0 * XS + 2 * kc];
                        ulonglong2 x1 = *(const ulonglong2*)&tb[r1 * XS + 2 * kc];
                        a00 = fma2(x0.x, w0[2 * kc], a00);
                        a01 = fma2(x0.x, w1[2 * kc], a01);
                        a10 = fma2(x1.x, w0[2 * kc], a10);
                        a11 = fma2(x1.x, w1[2 * kc], a11);
                        a00 = fma2(x0.y, w0[2 * kc + 1], a00);
                        a01 = fma2(x0.y, w1[2 * kc + 1], a01);
                        a10 = fma2(x1.y, w0[2 * kc + 1], a10);
                        a11 = fma2(x1.y, w1[2 * kc + 1], a11);
                    }
                    float lo, hi;
                    float y00, y01, y10, y11;
                    unpack2(a00, lo, hi); y00 = lo + hi + ba;
                    unpack2(a01, lo, hi); y01 = lo + hi + bb;
                    unpack2(a10, lo, hi); y10 = lo + hi + ba;
                    unpack2(a11, lo, hi); y11 = lo + hi + bb;
                    int g0 = base + r0;
                    int g1 = base + r1;
                    if (g0 < M) {
                        *(float2*)(yout + (size_t)g0 * D + c0) = make_float2(y00, y01);
                        cs0 += y00; cq0 += y00 * y00;
                        cs1 += y01; cq1 += y01 * y01;
                    }
                    if (g1 < M) {
                        *(float2*)(yout + (size_t)g1 * D + c0) = make_float2(y10, y11);
                        cs0 += y10; cq0 += y10 * y10;
                        cs1 += y11; cq1 += y11 * y11;
                    }
                }
            }
        }
        bcomp = bfill;
        bfill = (bfill == 2) ? 0 : bfill + 1;
    }

    // ---- stats: L2 threads hold per-column partials ----
    if (isL2) {
        int rep = ((blockIdx.x << 2) | wsub) & (NREP - 1);
        atomicAdd(&g_sum[target][rep][c0], cs0);
        atomicAdd(&g_sum[target][rep][c0 + 1], cs1);
        atomicAdd(&g_sq[target][rep][c0], cq0);
        atomicAdd(&g_sq[target][rep][c0 + 1], cq1);
    }
}

// ---------------- K3: finalize mean / rstd ----------------
__global__ void stats_kernel(int N, int E) {
    int t = threadIdx.x;
    int target = t >> 6;
    int c = t & 63;
    float s = 0.f, q = 0.f;
#pragma unroll
    for (int r = 0; r < NREP; ++r) { s += g_sum[target][r][c]; q += g_sq[target][r][c]; }
    float cnt = target ? (float)E : (float)N;
    float m = s / cnt;
    float var = q / cnt - m * m;
    g_mean[target][c] = m;
    g_rstd[target][c] = rsqrtf(var + 1e-5f);
}

// ---------------- K4: normalize + relu + residual, nodes+edges in one grid ----------------
__global__ void apply_kernel(const float* __restrict__ h,
                             const float* __restrict__ e,
                             const float* __restrict__ gh, const float* __restrict__ bh,
                             const float* __restrict__ ge, const float* __restrict__ be,
                             float* __restrict__ out, int N, int E) {
    int idx = blockIdx.x * blockDim.x + threadIdx.x;
    int ntot = N * 16;
    int total = ntot + E * 16;
    if (idx >= total) return;
    int target, lidx;
    const float* res;
    const float* gamma;
    const float* beta;
    if (idx < ntot) { target = 0; lidx = idx; res = h; gamma = gh; beta = bh; }
    else { target = 1; lidx = idx - ntot; res = e; gamma = ge; beta = be; }
    int r = lidx >> 4;
    int c4 = lidx & 15;
    size_t off = (size_t)r * D + c4 * 4;
    float* y = out + (target ? (size_t)N * D : 0);
    float4 v = *(float4*)(y + off);
    float4 rs = __ldg((const float4*)res + (off >> 2));
    float4 g = __ldg((const float4*)gamma + c4);
    float4 b = __ldg((const float4*)beta + c4);
    int c = c4 * 4;
    float4 m = *(const float4*)&g_mean[target][c];
    float4 sd = *(const float4*)&g_rstd[target][c];
    float4 o;
    o.x = rs.x + fmaxf(g.x * (v.x - m.x) * sd.x + b.x, 0.f);
    o.y = rs.y + fmaxf(g.y * (v.y - m.y) * sd.y + b.y, 0.f);
    o.z = rs.z + fmaxf(g.z * (v.z - m.z) * sd.z + b.z, 0.f);
    o.w = rs.w + fmaxf(g.w * (v.w - m.w) * sd.w + b.w, 0.f);
    *(float4*)(y + off) = o;
}

// ---------------- launcher ----------------
extern "C" void kernel_launch(void* const* d_in, const int* in_sizes, int n_in,
                              void* d_out, int out_size) {
    const float* h   = (const float*)d_in[0];
    const float* e   = (const float*)d_in[1];
    const int*   src = (const int*)d_in[2];
    const int*   dst = (const int*)d_in[3];
    const float* eps = (const float*)d_in[4];
    const float* W1  = (const float*)d_in[5];
    const float* b1  = (const float*)d_in[6];
    const float* W2  = (const float*)d_in[7];
    const float* b2  = (const float*)d_in[8];
    const float* gh  = (const float*)d_in[9];
    const float* bh  = (const float*)d_in[10];
    const float* ge  = (const float*)d_in[11];
    const float* be  = (const float*)d_in[12];

    int N = in_sizes[0] / D;
    int E = in_sizes[1] / D;
    float* out_h = (float*)d_out;

    cudaFuncSetAttribute(mlp_ws_kernel, cudaFuncAttributeMaxDynamicSharedMemorySize, SMEM_BYTES);

    int nblk = (N + TILE - 1) / TILE;
    int eblk = (E + TILE - 1) / TILE;

    zero_neigh_kernel<<<1024, 256>>>();                                   // 0
    init_kernel<<<(2 * NREP * D + 255) / 256, 256>>>(W1, W2);             // 1
    scatter_kernel<<<(E * 16 + 255) / 256, 256>>>(h, src, dst, E);        // 2

    mlp_ws_kernel<<<nblk + eblk, 256, SMEM_BYTES>>>(h, e, eps, b1, b2,
                                                    out_h, N, E, nblk);   // 3

    stats_kernel<<<1, 128>>>(N, E);                                       // 4

    apply_kernel<<<((N + E) * 16 + 255) / 256, 256>>>(h, e, gh, bh, ge, be,
                                                      out_h, N, E);       // 5
}

// round 16
// speedup vs baseline: 1.5130x; 1.5130x over previous
#include <cuda_runtime.h>
#include <cuda_bf16.h>
#include <cstdint>

#define D 64
#define CH 64              // rows per pipeline chunk
#define TILE 1024          // rows per CTA
#define NSTEP (TILE / CH)  // 16
#define XS 34              // u64 stride per row (32 data + 2 pad, 16B-aligned)
#define BUF (CH * XS)
#define NREP 64
#define MAX_N 100000

// ---------------- scratch (device globals) ----------------
__device__ float g_neigh[MAX_N * D];
__device__ float g_sum[2][NREP][D];
__device__ float g_sq[2][NREP][D];
__device__ __align__(16) float g_mean[2][D];
__device__ __align__(16) float g_rstd[2][D];
// k-paired weights: g_Wp[layer][kw][c] = (W[2kw][c], W[2kw+1][c]); row 16B-aligned
__device__ __align__(16) unsigned long long g_Wp[2][32][64];

// ---------------- packed fp32x2 helpers ----------------
__device__ __forceinline__ unsigned long long pack64(float lo, float hi) {
    unsigned long long r;
    asm("mov.b64 %0, {%1, %2};" : "=l"(r) : "f"(lo), "f"(hi));
    return r;
}
__device__ __forceinline__ void unpack2(unsigned long long v, float& lo, float& hi) {
    asm("mov.b64 {%0, %1}, %2;" : "=f"(lo), "=f"(hi) : "l"(v));
}
__device__ __forceinline__ unsigned long long fma2(unsigned long long a,
                                                   unsigned long long b,
                                                   unsigned long long c) {
    unsigned long long d;
    asm("fma.rn.f32x2 %0, %1, %2, %3;" : "=l"(d) : "l"(a), "l"(b), "l"(c));
    return d;
}
__device__ __forceinline__ uint32_t s2u(const void* p) {
    uint32_t a;
    asm("{ .reg .u64 t; cvta.to.shared.u64 t, %1; cvt.u32.u64 %0, t; }" : "=r"(a) : "l"(p));
    return a;
}

// ---------------- K0a: zero neigh ----------------
__global__ void zero_neigh_kernel() {
    int tid = blockIdx.x * blockDim.x + threadIdx.x;
    int stride = gridDim.x * blockDim.x;
    float4* p = (float4*)g_neigh;
    const int n4 = MAX_N * D / 4;
    for (int i = tid; i < n4; i += stride) p[i] = make_float4(0.f, 0.f, 0.f, 0.f);
}

// ---------------- K0b: zero stats + build k-paired W ----------------
__global__ void init_kernel(const float* __restrict__ W1, const float* __restrict__ W2) {
    int i = blockIdx.x * blockDim.x + threadIdx.x;
    if (i < 2 * NREP * D) {
        (&g_sum[0][0][0])[i] = 0.f;
        (&g_sq[0][0][0])[i] = 0.f;
    }
    if (i >= 2 * 32 * 64) return;
    int layer = i >> 11;
    int kw = (i >> 6) & 31;
    int c = i & 63;
    const float* W = layer ? W2 : W1;
    g_Wp[layer][kw][c] = pack64(__ldg(&W[(2 * kw) * D + c]),
                                __ldg(&W[(2 * kw + 1) * D + c]));
}

// ---------------- K1: scatter-sum  neigh[dst] += h[src] ----------------
__global__ void scatter_kernel(const float* __restrict__ h,
                               const int* __restrict__ src,
                               const int* __restrict__ dst, int E) {
    int idx = blockIdx.x * blockDim.x + threadIdx.x;
    int total = E * 16;
    if (idx >= total) return;
    int e = idx >> 4;
    int c = idx & 15;
    int s = __ldg(&src[e]);
    int d = __ldg(&dst[e]);
    float4 v = __ldg((const float4*)(h + (size_t)s * D) + c);
    float* p = g_neigh + (size_t)d * D + c * 4;
    asm volatile("red.global.add.v4.f32 [%0], {%1, %2, %3, %4};"
                 :: "l"(p), "f"(v.x), "f"(v.y), "f"(v.z), "f"(v.w) : "memory");
}

// ---------------- K2: combine hn = (1+eps)h + neigh into g_neigh ----------------
__global__ void combine_kernel(const float* __restrict__ h,
                               const float* __restrict__ epsp, int N) {
    int idx = blockIdx.x * blockDim.x + threadIdx.x;
    if (idx >= N * 16) return;
    float epsv = 1.f + __ldg(&epsp[0]);
    float4 a = __ldg((const float4*)h + idx);
    float4* pn = (float4*)g_neigh + idx;
    float4 n = *pn;
    n.x = fmaf(epsv, a.x, n.x);
    n.y = fmaf(epsv, a.y, n.y);
    n.z = fmaf(epsv, a.z, n.z);
    n.w = fmaf(epsv, a.w, n.w);
    *pn = n;
}

// async fill of one chunk (cp.async, zero-fill OOB tail); 256 threads
__device__ __forceinline__ void fill_async(unsigned long long* xb,
                                           const float* __restrict__ xsrc,
                                           int base, int M, int tid) {
#pragma unroll
    for (int t = 0; t < 4; ++t) {
        int idx = tid + t * 256;
        int r = idx >> 4;
        int c4 = idx & 15;
        int gr = base + r;
        unsigned long long* sp = &xb[r * XS + 2 * c4];
        if (gr < M) {
            uint32_t sa = s2u(sp);
            const float4* ga = (const float4*)(xsrc + (size_t)gr * D) + c4;
            asm volatile("cp.async.ca.shared.global [%0], [%1], 16;"
                         :: "r"(sa), "l"(ga) : "memory");
        } else {
            *(ulonglong2*)sp = make_ulonglong2(0ull, 0ull);
        }
    }
}

#define SMEM_BYTES ((3 + 2) * BUF * 8)

// ---------------- K3: weight-stationary MLP, 2 cols/thread, single barrier/step ----------------
__global__ void __launch_bounds__(256, 1)
mlp_ws_kernel(const float* __restrict__ ein,
              const float* __restrict__ b1, const float* __restrict__ b2,
              float* __restrict__ out, int N, int E, int nblk) {
    extern __shared__ unsigned long long smem[];
    unsigned long long* xs = smem;            // 3 buffers
    unsigned long long* ts = smem + 3 * BUF;  // 2 buffers

    int tid = threadIdx.x;
    int wid = tid >> 5;
    int lane = tid & 31;
    int isL2 = wid >> 2;       // warps 0-3: layer1, warps 4-7: layer2
    int wsub = wid & 3;        // row group within layer
    int c0 = 2 * lane;         // this thread's column pair
    int rbase = wsub * 16;     // 16 rows per warp per chunk

    int target, row0, M;
    const float* xsrc;
    float* yout;
    if (blockIdx.x < nblk) {
        target = 0; row0 = blockIdx.x * TILE; M = N; xsrc = g_neigh; yout = out;
    } else {
        target = 1; row0 = (blockIdx.x - nblk) * TILE; M = E; xsrc = ein;
        yout = out + (size_t)N * D;
    }

    // resident weights: columns c0, c0+1, loaded as LDG.128 pairs
    unsigned long long w0[32], w1[32];
    {
        const unsigned long long* Wp = &g_Wp[isL2][0][0];
#pragma unroll
        for (int kw = 0; kw < 32; ++kw) {
            ulonglong2 wp = __ldg((const ulonglong2*)(Wp + kw * 64 + c0));
            w0[kw] = wp.x;
            w1[kw] = wp.y;
        }
    }
    const float* bias = isL2 ? b2 : b1;
    float ba = __ldg(&bias[c0]);
    float bb = __ldg(&bias[c0 + 1]);

    float cs0 = 0.f, cs1 = 0.f, cq0 = 0.f, cq1 = 0.f;

    fill_async(xs, xsrc, row0, M, tid);   // buffer 0
    asm volatile("cp.async.commit_group;" ::: "memory");

    int bfill = 1, bcomp = 0;
    for (int s = 0; s <= NSTEP; ++s) {
        if (s + 1 < NSTEP)
            fill_async(xs + bfill * BUF, xsrc, row0 + (s + 1) * CH, M, tid);
        asm volatile("cp.async.commit_group;" ::: "memory");
        asm volatile("cp.async.wait_group 1;" ::: "memory");
        __syncthreads();   // xs[bcomp] visible to all; ts[s-1] writes visible to L2

        if (!isL2) {
            if (s < NSTEP) {
                const unsigned long long* xb = xs + bcomp * BUF;
                float* tb = (float*)(ts + (s & 1) * BUF);
#pragma unroll
                for (int rr = 0; rr < 16; rr += 2) {
                    int r0 = rbase + rr;
                    int r1 = r0 + 1;
                    unsigned long long a00 = 0ull, a01 = 0ull, a10 = 0ull, a11 = 0ull;
#pragma unroll
                    for (int kc = 0; kc < 16; ++kc) {
                        ulonglong2 x0 = *(const ulonglong2*)&xb[r0 * XS + 2 * kc];
                        ulonglong2 x1 = *(const ulonglong2*)&xb[r1 * XS + 2 * kc];
                        a00 = fma2(x0.x, w0[2 * kc], a00);
                        a01 = fma2(x0.x, w1[2 * kc], a01);
                        a10 = fma2(x1.x, w0[2 * kc], a10);
                        a11 = fma2(x1.x, w1[2 * kc], a11);
                        a00 = fma2(x0.y, w0[2 * kc + 1], a00);
                        a01 = fma2(x0.y, w1[2 * kc + 1], a01);
                        a10 = fma2(x1.y, w0[2 * kc + 1], a10);
                        a11 = fma2(x1.y, w1[2 * kc + 1], a11);
                    }
                    float lo, hi, t0, t1;
                    unpack2(a00, lo, hi); t0 = fmaxf(lo + hi + ba, 0.f);
                    unpack2(a01, lo, hi); t1 = fmaxf(lo + hi + bb, 0.f);
                    *(float2*)&tb[r0 * (2 * XS) + c0] = make_float2(t0, t1);
                    unpack2(a10, lo, hi); t0 = fmaxf(lo + hi + ba, 0.f);
                    unpack2(a11, lo, hi); t1 = fmaxf(lo + hi + bb, 0.f);
                    *(float2*)&tb[r1 * (2 * XS) + c0] = make_float2(t0, t1);
                }
            }
        } else {
            if (s >= 1) {
                int sc = s - 1;
                int base = row0 + sc * CH;
                const unsigned long long* tb = ts + (sc & 1) * BUF;
#pragma unroll
                for (int rr = 0; rr < 16; rr += 2) {
                    int r0 = rbase + rr;
                    int r1 = r0 + 1;
                    unsigned long long a00 = 0ull, a01 = 0ull, a10 = 0ull, a11 = 0ull;
#pragma unroll
                    for (int kc = 0; kc < 16; ++kc) {
                        ulonglong2 x0 = *(const ulonglong2*)&tb[r0 * XS + 2 * kc];
                        ulonglong2 x1 = *(const ulonglong2*)&tb[r1 * XS + 2 * kc];
                        a00 = fma2(x0.x, w0[2 * kc], a00);
                        a01 = fma2(x0.x, w1[2 * kc], a01);
                        a10 = fma2(x1.x, w0[2 * kc], a10);
                        a11 = fma2(x1.x, w1[2 * kc], a11);
                        a00 = fma2(x0.y, w0[2 * kc + 1], a00);
                        a01 = fma2(x0.y, w1[2 * kc + 1], a01);
                        a10 = fma2(x1.y, w0[2 * kc + 1], a10);
                        a11 = fma2(x1.y, w1[2 * kc + 1], a11);
                    }
                    float lo, hi;
                    float y00, y01, y10, y11;
                    unpack2(a00, lo, hi); y00 = lo + hi + ba;
                    unpack2(a01, lo, hi); y01 = lo + hi + bb;
                    unpack2(a10, lo, hi); y10 = lo + hi + ba;
                    unpack2(a11, lo, hi); y11 = lo + hi + bb;
                    int g0 = base + r0;
                    int g1 = base + r1;
                    if (g0 < M) {
                        *(float2*)(yout + (size_t)g0 * D + c0) = make_float2(y00, y01);
                        cs0 += y00; cq0 += y00 * y00;
                        cs1 += y01; cq1 += y01 * y01;
                    }
                    if (g1 < M) {
                        *(float2*)(yout + (size_t)g1 * D + c0) = make_float2(y10, y11);
                        cs0 += y10; cq0 += y10 * y10;
                        cs1 += y11; cq1 += y11 * y11;
                    }
                }
            }
        }
        bcomp = bfill;
        bfill = (bfill == 2) ? 0 : bfill + 1;
    }

    // ---- stats: L2 threads hold per-column partials ----
    if (isL2) {
        int rep = ((blockIdx.x << 2) | wsub) & (NREP - 1);
        atomicAdd(&g_sum[target][rep][c0], cs0);
        atomicAdd(&g_sum[target][rep][c0 + 1], cs1);
        atomicAdd(&g_sq[target][rep][c0], cq0);
        atomicAdd(&g_sq[target][rep][c0 + 1], cq1);
    }
}

// ---------------- K4: finalize mean / rstd ----------------
__global__ void stats_kernel(int N, int E) {
    int t = threadIdx.x;
    int target = t >> 6;
    int c = t & 63;
    float s = 0.f, q = 0.f;
#pragma unroll
    for (int r = 0; r < NREP; ++r) { s += g_sum[target][r][c]; q += g_sq[target][r][c]; }
    float cnt = target ? (float)E : (float)N;
    float m = s / cnt;
    float var = q / cnt - m * m;
    g_mean[target][c] = m;
    g_rstd[target][c] = rsqrtf(var + 1e-5f);
}

// ---------------- K5: normalize + relu + residual, nodes+edges in one grid ----------------
__global__ void apply_kernel(const float* __restrict__ h,
                             const float* __restrict__ e,
                             const float* __restrict__ gh, const float* __restrict__ bh,
                             const float* __restrict__ ge, const float* __restrict__ be,
                             float* __restrict__ out, int N, int E) {
    int idx = blockIdx.x * blockDim.x + threadIdx.x;
    int ntot = N * 16;
    int total = ntot + E * 16;
    if (idx >= total) return;
    int target, lidx;
    const float* res;
    const float* gamma;
    const float* beta;
    if (idx < ntot) { target = 0; lidx = idx; res = h; gamma = gh; beta = bh; }
    else { target = 1; lidx = idx - ntot; res = e; gamma = ge; beta = be; }
    int r = lidx >> 4;
    int c4 = lidx & 15;
    size_t off = (size_t)r * D + c4 * 4;
    float* y = out + (target ? (size_t)N * D : 0);
    float4 v = *(float4*)(y + off);
    float4 rs = __ldg((const float4*)res + (off >> 2));
    float4 g = __ldg((const float4*)gamma + c4);
    float4 b = __ldg((const float4*)beta + c4);
    int c = c4 * 4;
    float4 m = *(const float4*)&g_mean[target][c];
    float4 sd = *(const float4*)&g_rstd[target][c];
    float4 o;
    o.x = rs.x + fmaxf(g.x * (v.x - m.x) * sd.x + b.x, 0.f);
    o.y = rs.y + fmaxf(g.y * (v.y - m.y) * sd.y + b.y, 0.f);
    o.z = rs.z + fmaxf(g.z * (v.z - m.z) * sd.z + b.z, 0.f);
    o.w = rs.w + fmaxf(g.w * (v.w - m.w) * sd.w + b.w, 0.f);
    *(float4*)(y + off) = o;
}

// ---------------- launcher ----------------
extern "C" void kernel_launch(void* const* d_in, const int* in_sizes, int n_in,
                              void* d_out, int out_size) {
    const float* h   = (const float*)d_in[0];
    const float* e   = (const float*)d_in[1];
    const int*   src = (const int*)d_in[2];
    const int*   dst = (const int*)d_in[3];
    const float* eps = (const float*)d_in[4];
    const float* W1  = (const float*)d_in[5];
    const float* b1  = (const float*)d_in[6];
    const float* W2  = (const float*)d_in[7];
    const float* b2  = (const float*)d_in[8];
    const float* gh  = (const float*)d_in[9];
    const float* bh  = (const float*)d_in[10];
    const float* ge  = (const float*)d_in[11];
    const float* be  = (const float*)d_in[12];

    int N = in_sizes[0] / D;
    int E = in_sizes[1] / D;
    float* out_h = (float*)d_out;

    cudaFuncSetAttribute(mlp_ws_kernel, cudaFuncAttributeMaxDynamicSharedMemorySize, SMEM_BYTES);

    int nblk = (N + TILE - 1) / TILE;
    int eblk = (E + TILE - 1) / TILE;

    zero_neigh_kernel<<<1024, 256>>>();                                   // 0
    init_kernel<<<(2 * NREP * D + 255) / 256, 256>>>(W1, W2);             // 1
    scatter_kernel<<<(E * 16 + 255) / 256, 256>>>(h, src, dst, E);        // 2
    combine_kernel<<<(N * 16 + 255) / 256, 256>>>(h, eps, N);             // 3

    mlp_ws_kernel<<<nblk + eblk, 256, SMEM_BYTES>>>(e, b1, b2,
                                                    out_h, N, E, nblk);   // 4

    stats_kernel<<<1, 128>>>(N, E);                                       // 5

    apply_kernel<<<((N + E) * 16 + 255) / 256, 256>>>(h, e, gh, bh, ge, be,
                                                      out_h, N, E);       // 6
}

// round 17
// speedup vs baseline: 1.5227x; 1.0064x over previous
#include <cuda_runtime.h>
#include <cuda_bf16.h>
#include <cstdint>

#define D 64
#define CH 128             // rows per pipeline chunk
#define TILE 1024          // rows per CTA
#define NSTEP (TILE / CH)  // 8
#define XS 34              // u64 stride per row (32 data + 2 pad, 16B-aligned)
#define BUF (CH * XS)
#define NREP 64
#define MAX_N 100000

// ---------------- scratch (device globals) ----------------
__device__ float g_neigh[MAX_N * D];
__device__ float g_sum[2][NREP][D];
__device__ float g_sq[2][NREP][D];
__device__ __align__(16) float g_mean[2][D];
__device__ __align__(16) float g_rstd[2][D];
// k-paired weights: g_Wp[layer][kw][c] = (W[2kw][c], W[2kw+1][c]); row 16B-aligned
__device__ __align__(16) unsigned long long g_Wp[2][32][64];

// ---------------- packed fp32x2 helpers ----------------
__device__ __forceinline__ unsigned long long pack64(float lo, float hi) {
    unsigned long long r;
    asm("mov.b64 %0, {%1, %2};" : "=l"(r) : "f"(lo), "f"(hi));
    return r;
}
__device__ __forceinline__ void unpack2(unsigned long long v, float& lo, float& hi) {
    asm("mov.b64 {%0, %1}, %2;" : "=f"(lo), "=f"(hi) : "l"(v));
}
__device__ __forceinline__ unsigned long long fma2(unsigned long long a,
                                                   unsigned long long b,
                                                   unsigned long long c) {
    unsigned long long d;
    asm("fma.rn.f32x2 %0, %1, %2, %3;" : "=l"(d) : "l"(a), "l"(b), "l"(c));
    return d;
}
__device__ __forceinline__ uint32_t s2u(const void* p) {
    uint32_t a;
    asm("{ .reg .u64 t; cvta.to.shared.u64 t, %1; cvt.u32.u64 %0, t; }" : "=r"(a) : "l"(p));
    return a;
}

// ---------------- K0a: init neigh = (1+eps)*h  (combine folded into init) ----------------
__global__ void init_neigh_kernel(const float* __restrict__ h,
                                  const float* __restrict__ epsp, int N) {
    int idx = blockIdx.x * blockDim.x + threadIdx.x;
    if (idx >= N * 16) return;
    float epsv = 1.f + __ldg(&epsp[0]);
    float4 a = __ldg((const float4*)h + idx);
    float4 v;
    v.x = epsv * a.x; v.y = epsv * a.y; v.z = epsv * a.z; v.w = epsv * a.w;
    ((float4*)g_neigh)[idx] = v;
}

// ---------------- K0b: zero stats + build k-paired W ----------------
__global__ void init_kernel(const float* __restrict__ W1, const float* __restrict__ W2) {
    int i = blockIdx.x * blockDim.x + threadIdx.x;
    if (i < 2 * NREP * D) {
        (&g_sum[0][0][0])[i] = 0.f;
        (&g_sq[0][0][0])[i] = 0.f;
    }
    if (i >= 2 * 32 * 64) return;
    int layer = i >> 11;
    int kw = (i >> 6) & 31;
    int c = i & 63;
    const float* W = layer ? W2 : W1;
    g_Wp[layer][kw][c] = pack64(__ldg(&W[(2 * kw) * D + c]),
                                __ldg(&W[(2 * kw + 1) * D + c]));
}

// ---------------- K1: scatter-sum  neigh[dst] += h[src] ----------------
__global__ void scatter_kernel(const float* __restrict__ h,
                               const int* __restrict__ src,
                               const int* __restrict__ dst, int E) {
    int idx = blockIdx.x * blockDim.x + threadIdx.x;
    int total = E * 16;
    if (idx >= total) return;
    int e = idx >> 4;
    int c = idx & 15;
    int s = __ldg(&src[e]);
    int d = __ldg(&dst[e]);
    float4 v = __ldg((const float4*)(h + (size_t)s * D) + c);
    float* p = g_neigh + (size_t)d * D + c * 4;
    asm volatile("red.global.add.v4.f32 [%0], {%1, %2, %3, %4};"
                 :: "l"(p), "f"(v.x), "f"(v.y), "f"(v.z), "f"(v.w) : "memory");
}

// async fill of one chunk (cp.async, zero-fill OOB tail); 256 threads
__device__ __forceinline__ void fill_async(unsigned long long* xb,
                                           const float* __restrict__ xsrc,
                                           int base, int M, int tid) {
#pragma unroll
    for (int t = 0; t < CH / 16; ++t) {
        int idx = tid + t * 256;
        int r = idx >> 4;
        int c4 = idx & 15;
        int gr = base + r;
        unsigned long long* sp = &xb[r * XS + 2 * c4];
        if (gr < M) {
            uint32_t sa = s2u(sp);
            const float4* ga = (const float4*)(xsrc + (size_t)gr * D) + c4;
            asm volatile("cp.async.ca.shared.global [%0], [%1], 16;"
                         :: "r"(sa), "l"(ga) : "memory");
        } else {
            *(ulonglong2*)sp = make_ulonglong2(0ull, 0ull);
        }
    }
}

#define SMEM_BYTES ((3 + 2) * BUF * 8)

// ---------------- K2: weight-stationary MLP, 2 cols/thread, single barrier/step ----------------
__global__ void __launch_bounds__(256, 1)
mlp_ws_kernel(const float* __restrict__ ein,
              const float* __restrict__ b1, const float* __restrict__ b2,
              float* __restrict__ out, int N, int E, int nblk) {
    extern __shared__ unsigned long long smem[];
    unsigned long long* xs = smem;            // 3 buffers
    unsigned long long* ts = smem + 3 * BUF;  // 2 buffers

    int tid = threadIdx.x;
    int wid = tid >> 5;
    int lane = tid & 31;
    int isL2 = wid >> 2;       // warps 0-3: layer1, warps 4-7: layer2
    int wsub = wid & 3;        // row group within layer
    int c0 = 2 * lane;         // this thread's column pair
    int rbase = wsub * (CH / 4);   // 32 rows per warp per chunk

    int target, row0, M;
    const float* xsrc;
    float* yout;
    if (blockIdx.x < nblk) {
        target = 0; row0 = blockIdx.x * TILE; M = N; xsrc = g_neigh; yout = out;
    } else {
        target = 1; row0 = (blockIdx.x - nblk) * TILE; M = E; xsrc = ein;
        yout = out + (size_t)N * D;
    }

    // resident weights: columns c0, c0+1, loaded as LDG.128 pairs
    unsigned long long w0[32], w1[32];
    {
        const unsigned long long* Wp = &g_Wp[isL2][0][0];
#pragma unroll
        for (int kw = 0; kw < 32; ++kw) {
            ulonglong2 wp = __ldg((const ulonglong2*)(Wp + kw * 64 + c0));
            w0[kw] = wp.x;
            w1[kw] = wp.y;
        }
    }
    const float* bias = isL2 ? b2 : b1;
    float ba = __ldg(&bias[c0]);
    float bb = __ldg(&bias[c0 + 1]);

    float cs0 = 0.f, cs1 = 0.f, cq0 = 0.f, cq1 = 0.f;

    fill_async(xs, xsrc, row0, M, tid);   // buffer 0
    asm volatile("cp.async.commit_group;" ::: "memory");

    int bfill = 1, bcomp = 0;
    for (int s = 0; s <= NSTEP; ++s) {
        if (s + 1 < NSTEP)
            fill_async(xs + bfill * BUF, xsrc, row0 + (s + 1) * CH, M, tid);
        asm volatile("cp.async.commit_group;" ::: "memory");
        asm volatile("cp.async.wait_group 1;" ::: "memory");
        __syncthreads();   // xs[bcomp] visible to all; ts[s-1] writes visible to L2

        if (!isL2) {
            if (s < NSTEP) {
                const unsigned long long* xb = xs + bcomp * BUF;
                float* tb = (float*)(ts + (s & 1) * BUF);
#pragma unroll
                for (int rr = 0; rr < CH / 4; rr += 2) {
                    int r0 = rbase + rr;
                    int r1 = r0 + 1;
                    unsigned long long a00 = 0ull, a01 = 0ull, a10 = 0ull, a11 = 0ull;
#pragma unroll
                    for (int kc = 0; kc < 16; ++kc) {
                        ulonglong2 x0 = *(const ulonglong2*)&xb[r0 * XS + 2 * kc];
                        ulonglong2 x1 = *(const ulonglong2*)&xb[r1 * XS + 2 * kc];
                        a00 = fma2(x0.x, w0[2 * kc], a00);
                        a01 = fma2(x0.x, w1[2 * kc], a01);
                        a10 = fma2(x1.x, w0[2 * kc], a10);
                        a11 = fma2(x1.x, w1[2 * kc], a11);
                        a00 = fma2(x0.y, w0[2 * kc + 1], a00);
                        a01 = fma2(x0.y, w1[2 * kc + 1], a01);
                        a10 = fma2(x1.y, w0[2 * kc + 1], a10);
                        a11 = fma2(x1.y, w1[2 * kc + 1], a11);
                    }
                    float lo, hi, t0, t1;
                    unpack2(a00, lo, hi); t0 = fmaxf(lo + hi + ba, 0.f);
                    unpack2(a01, lo, hi); t1 = fmaxf(lo + hi + bb, 0.f);
                    *(float2*)&tb[r0 * (2 * XS) + c0] = make_float2(t0, t1);
                    unpack2(a10, lo, hi); t0 = fmaxf(lo + hi + ba, 0.f);
                    unpack2(a11, lo, hi); t1 = fmaxf(lo + hi + bb, 0.f);
                    *(float2*)&tb[r1 * (2 * XS) + c0] = make_float2(t0, t1);
                }
            }
        } else {
            if (s >= 1) {
                int sc = s - 1;
                int base = row0 + sc * CH;
                const unsigned long long* tb = ts + (sc & 1) * BUF;
#pragma unroll
                for (int rr = 0; rr < CH / 4; rr += 2) {
                    int r0 = rbase + rr;
                    int r1 = r0 + 1;
                    unsigned long long a00 = 0ull, a01 = 0ull, a10 = 0ull, a11 = 0ull;
#pragma unroll
                    for (int kc = 0; kc < 16; ++kc) {
                        ulonglong2 x0 = *(const ulonglong2*)&tb[r0 * XS + 2 * kc];
                        ulonglong2 x1 = *(const ulonglong2*)&tb[r1 * XS + 2 * kc];
                        a00 = fma2(x0.x, w0[2 * kc], a00);
                        a01 = fma2(x0.x, w1[2 * kc], a01);
                        a10 = fma2(x1.x, w0[2 * kc], a10);
                        a11 = fma2(x1.x, w1[2 * kc], a11);
                        a00 = fma2(x0.y, w0[2 * kc + 1], a00);
                        a01 = fma2(x0.y, w1[2 * kc + 1], a01);
                        a10 = fma2(x1.y, w0[2 * kc + 1], a10);
                        a11 = fma2(x1.y, w1[2 * kc + 1], a11);
                    }
                    float lo, hi;
                    float y00, y01, y10, y11;
                    unpack2(a00, lo, hi); y00 = lo + hi + ba;
                    unpack2(a01, lo, hi); y01 = lo + hi + bb;
                    unpack2(a10, lo, hi); y10 = lo + hi + ba;
                    unpack2(a11, lo, hi); y11 = lo + hi + bb;
                    int g0 = base + r0;
                    int g1 = base + r1;
                    if (g0 < M) {
                        *(float2*)(yout + (size_t)g0 * D + c0) = make_float2(y00, y01);
                        cs0 += y00; cq0 += y00 * y00;
                        cs1 += y01; cq1 += y01 * y01;
                    }
                    if (g1 < M) {
                        *(float2*)(yout + (size_t)g1 * D + c0) = make_float2(y10, y11);
                        cs0 += y10; cq0 += y10 * y10;
                        cs1 += y11; cq1 += y11 * y11;
                    }
                }
            }
        }
        bcomp = bfill;
        bfill = (bfill == 2) ? 0 : bfill + 1;
    }

    // ---- stats: L2 threads hold per-column partials ----
    if (isL2) {
        int rep = ((blockIdx.x << 2) | wsub) & (NREP - 1);
        atomicAdd(&g_sum[target][rep][c0], cs0);
        atomicAdd(&g_sum[target][rep][c0 + 1], cs1);
        atomicAdd(&g_sq[target][rep][c0], cq0);
        atomicAdd(&g_sq[target][rep][c0 + 1], cq1);
    }
}

// ---------------- K3: finalize mean / rstd ----------------
__global__ void stats_kernel(int N, int E) {
    int t = threadIdx.x;
    int target = t >> 6;
    int c = t & 63;
    float s = 0.f, q = 0.f;
#pragma unroll
    for (int r = 0; r < NREP; ++r) { s += g_sum[target][r][c]; q += g_sq[target][r][c]; }
    float cnt = target ? (float)E : (float)N;
    float m = s / cnt;
    float var = q / cnt - m * m;
    g_mean[target][c] = m;
    g_rstd[target][c] = rsqrtf(var + 1e-5f);
}

// ---------------- K4: normalize + relu + residual, nodes+edges in one grid ----------------
__global__ void apply_kernel(const float* __restrict__ h,
                             const float* __restrict__ e,
                             const float* __restrict__ gh, const float* __restrict__ bh,
                             const float* __restrict__ ge, const float* __restrict__ be,
                             float* __restrict__ out, int N, int E) {
    int idx = blockIdx.x * blockDim.x + threadIdx.x;
    int ntot = N * 16;
    int total = ntot + E * 16;
    if (idx >= total) return;
    int target, lidx;
    const float* res;
    const float* gamma;
    const float* beta;
    if (idx < ntot) { target = 0; lidx = idx; res = h; gamma = gh; beta = bh; }
    else { target = 1; lidx = idx - ntot; res = e; gamma = ge; beta = be; }
    int r = lidx >> 4;
    int c4 = lidx & 15;
    size_t off = (size_t)r * D + c4 * 4;
    float* y = out + (target ? (size_t)N * D : 0);
    float4 v = *(float4*)(y + off);
    float4 rs = __ldg((const float4*)res + (off >> 2));
    float4 g = __ldg((const float4*)gamma + c4);
    float4 b = __ldg((const float4*)beta + c4);
    int c = c4 * 4;
    float4 m = *(const float4*)&g_mean[target][c];
    float4 sd = *(const float4*)&g_rstd[target][c];
    float4 o;
    o.x = rs.x + fmaxf(g.x * (v.x - m.x) * sd.x + b.x, 0.f);
    o.y = rs.y + fmaxf(g.y * (v.y - m.y) * sd.y + b.y, 0.f);
    o.z = rs.z + fmaxf(g.z * (v.z - m.z) * sd.z + b.z, 0.f);
    o.w = rs.w + fmaxf(g.w * (v.w - m.w) * sd.w + b.w, 0.f);
    *(float4*)(y + off) = o;
}

// ---------------- launcher ----------------
extern "C" void kernel_launch(void* const* d_in, const int* in_sizes, int n_in,
                              void* d_out, int out_size) {
    const float* h   = (const float*)d_in[0];
    const float* e   = (const float*)d_in[1];
    const int*   src = (const int*)d_in[2];
    const int*   dst = (const int*)d_in[3];
    const float* eps = (const float*)d_in[4];
    const float* W1  = (const float*)d_in[5];
    const float* b1  = (const float*)d_in[6];
    const float* W2  = (const float*)d_in[7];
    const float* b2  = (const float*)d_in[8];
    const float* gh  = (const float*)d_in[9];
    const float* bh  = (const float*)d_in[10];
    const float* ge  = (const float*)d_in[11];
    const float* be  = (const float*)d_in[12];

    int N = in_sizes[0] / D;
    int E = in_sizes[1] / D;
    float* out_h = (float*)d_out;

    cudaFuncSetAttribute(mlp_ws_kernel, cudaFuncAttributeMaxDynamicSharedMemorySize, SMEM_BYTES);

    int nblk = (N + TILE - 1) / TILE;
    int eblk = (E + TILE - 1) / TILE;

    init_neigh_kernel<<<(N * 16 + 255) / 256, 256>>>(h, eps, N);          // 0
    init_kernel<<<(2 * NREP * D + 255) / 256, 256>>>(W1, W2);             // 1
    scatter_kernel<<<(E * 16 + 255) / 256, 256>>>(h, src, dst, E);        // 2

    mlp_ws_kernel<<<nblk + eblk, 256, SMEM_BYTES>>>(e, b1, b2,
                                                    out_h, N, E, nblk);   // 3

    stats_kernel<<<1, 128>>>(N, E);                                       // 4

    apply_kernel<<<((N + E) * 16 + 255) / 256, 256>>>(h, e, gh, bh, ge, be,
                                                      out_h, N, E);       // 5
}